// round 14
// baseline (speedup 1.0000x reference)
#include <cuda_runtime.h>
#include <cuda_bf16.h>
#include <math.h>
#include <stdint.h>

#define Bb 2
#define Ss 1024
#define Dd 1024
#define Ee 64
#define Nn 16
#define Mtot (Bb * Ss)

// ---------------- scratch (no allocation allowed) ----------------
__device__ float g_A[Bb * Ss * Ss];        // QK^T/sqrt(d) fp32
__device__ float g_comb[Bb * Ss * Dd];
__device__ float g_w[Bb * Nn * Ss];
__device__ __nv_bfloat16 g_xh[Mtot * Dd];
__device__ __nv_bfloat16 g_wqh[Dd * Dd];
__device__ __nv_bfloat16 g_wkh[Dd * Dd];
__device__ __nv_bfloat16 g_wvh[Dd * Dd];
__device__ __nv_bfloat16 g_Qh[Mtot * Dd];
__device__ __nv_bfloat16 g_Kh[Mtot * Dd];
__device__ __nv_bfloat16 g_Vth[Bb * Dd * Ss];   // V^T bf16, [b][d][s]
__device__ __nv_bfloat16 g_Ph[Bb * Ss * Ss];

// ---------------- helpers ----------------
__device__ __forceinline__ uint32_t smem_u32(const void* p) {
    uint32_t a;
    asm("{ .reg .u64 t; cvta.to.shared.u64 t, %1; cvt.u32.u64 %0, t; }" : "=r"(a) : "l"(p));
    return a;
}
__device__ __forceinline__ uint32_t sw128(uint32_t off) { return off ^ ((off >> 3) & 0x70); }

#define CP_ASYNC16(s, g) \
    asm volatile("cp.async.cg.shared.global [%0], [%1], 16;" :: "r"(s), "l"(g) : "memory")
#define CP_COMMIT() asm volatile("cp.async.commit_group;" ::: "memory")
template <int N>
__device__ __forceinline__ void cp_wait() {
    asm volatile("cp.async.wait_group %0;" :: "n"(N) : "memory");
}

#define LDSM_X4(r0, r1, r2, r3, addr) \
    asm volatile("ldmatrix.sync.aligned.m8n8.x4.shared.b16 {%0,%1,%2,%3}, [%4];" \
        : "=r"(r0), "=r"(r1), "=r"(r2), "=r"(r3) : "r"(addr) : "memory")

#define MMA16816(ac, a, b0, b1) \
    asm volatile("mma.sync.aligned.m16n8k16.row.col.f32.bf16.bf16.f32 " \
        "{%0,%1,%2,%3}, {%4,%5,%6,%7}, {%8,%9}, {%0,%1,%2,%3};" \
        : "+f"((ac)[0]), "+f"((ac)[1]), "+f"((ac)[2]), "+f"((ac)[3]) \
        : "r"((a)[0]), "r"((a)[1]), "r"((a)[2]), "r"((a)[3]), "r"(b0), "r"(b1))

// ---------------- reductions ----------------
__device__ __forceinline__ float warpSum(float v) {
    #pragma unroll
    for (int o = 16; o; o >>= 1) v += __shfl_xor_sync(0xffffffffu, v, o);
    return v;
}
__device__ __forceinline__ float blockSum(float v, float* red) {
    int lane = threadIdx.x & 31, w = threadIdx.x >> 5;
    v = warpSum(v);
    if (lane == 0) red[w] = v;
    __syncthreads();
    if (w == 0) {
        float t = (lane < 8) ? red[lane] : 0.0f;
        t = warpSum(t);
        if (lane == 0) red[8] = t;
    }
    __syncthreads();
    return red[8];
}

// ---------------- single-pass bf16 HMMA GEMM (round-12 champion config) ----------------
#define BKC 64

struct GemmArgs {
    const __nv_bfloat16* A; long long sA;
    const __nv_bfloat16 *B0, *B1, *B2; long long sB;
    float* Cf;
    __nv_bfloat16 *Cb0, *Cb1;
    __nv_bfloat16* Vt;
    long long sC;
    int M, N, K; float alpha;
};

// CAUSAL: 0=proj (Vt? transposed epilogue), 1=score (skip upper tiles), 2=PV (K-truncate)
template <int CAUSAL, int BMp, int BNp, int WM, int WN, int NST>
__global__ __launch_bounds__(256)
void hmma_gemm(GemmArgs g)
{
    constexpr int STG_A = BMp * 128;
    constexpr int STG_B = BNp * 128;
    constexpr int WTM = BMp / WM;
    constexpr int WTN = BNp / WN;
    constexpr int MF = WTM / 16;
    constexpr int NG = WTN / 16;
    constexpr int INFLT = NST - 1;

    const int bx = blockIdx.x, by = blockIdx.y, bz = blockIdx.z;
    if (CAUSAL == 1 && bx * BNp >= (by + 1) * BMp) return;
    int kEnd = g.K;
    if (CAUSAL == 2) kEnd = min(g.K, (by + 1) * BMp);
    const int NC = kEnd / BKC;

    extern __shared__ __align__(128) char dsm[];
    const uint32_t sAb = smem_u32(dsm);
    const uint32_t sBb = sAb + NST * STG_A;

    const int tid = threadIdx.x, wid = tid >> 5, lane = tid & 31;
    const int warpM = wid / WN, warpN = wid % WN;

    const __nv_bfloat16* Ah = g.A + bz * g.sA;
    const __nv_bfloat16* Bh = (bz == 0 ? g.B0 : bz == 1 ? g.B1 : g.B2) + bz * g.sB;

    float acc[MF][NG * 2][4];
    #pragma unroll
    for (int i = 0; i < MF; i++)
        #pragma unroll
        for (int j = 0; j < NG * 2; j++)
            #pragma unroll
            for (int k = 0; k < 4; k++) acc[i][j][k] = 0.0f;

    const int lc16 = tid & 7;
    const int lrow = tid >> 3;

    const __nv_bfloat16* Arow = Ah + (long long)(by * BMp) * g.K;
    const __nv_bfloat16* Brow = Bh + (long long)(bx * BNp) * g.K;
    const int Kld = g.K;

    auto issue = [&](int it, int buf) {
        const int k0 = it * BKC;
        const uint32_t aB = sAb + buf * STG_A;
        const uint32_t bB = sBb + buf * STG_B;
        #pragma unroll
        for (int r = 0; r < BMp / 32; r++) {
            const int row = lrow + 32 * r;
            CP_ASYNC16(aB + sw128(row * 128 + lc16 * 16),
                       Arow + (long long)row * Kld + k0 + lc16 * 8);
        }
        #pragma unroll
        for (int r = 0; r < BNp / 32; r++) {
            const int row = lrow + 32 * r;
            CP_ASYNC16(bB + sw128(row * 128 + lc16 * 16),
                       Brow + (long long)row * Kld + k0 + lc16 * 8);
        }
    };

    #pragma unroll
    for (int it = 0; it < INFLT; it++) {
        if (it < NC) issue(it, it);
        CP_COMMIT();
    }

    const int aRowL = (lane & 15);
    const int aHiK  = (lane >> 4);
    const int bRowL = ((lane & 16) >> 1) + (lane & 7);
    const int bHiK  = ((lane >> 3) & 1);

    #pragma unroll 1
    for (int it = 0; it < NC; it++) {
        cp_wait<NST - 2>();
        __syncthreads();
        const int nx = it + INFLT;
        if (nx < NC) issue(nx, nx % NST);
        CP_COMMIT();
        const int buf = it % NST;
        const uint32_t aB = sAb + buf * STG_A;
        const uint32_t bB = sBb + buf * STG_B;
        #pragma unroll
        for (int s = 0; s < 4; s++) {
            uint32_t ra[MF][4], rb[NG][4];
            #pragma unroll
            for (int mf = 0; mf < MF; mf++) {
                int row = warpM * WTM + mf * 16 + aRowL;
                int c16 = s * 2 + aHiK;
                LDSM_X4(ra[mf][0], ra[mf][1], ra[mf][2], ra[mf][3],
                        aB + sw128(row * 128 + c16 * 16));
            }
            #pragma unroll
            for (int ng = 0; ng < NG; ng++) {
                int nrow = warpN * WTN + ng * 16 + bRowL;
                int c16 = s * 2 + bHiK;
                LDSM_X4(rb[ng][0], rb[ng][1], rb[ng][2], rb[ng][3],
                        bB + sw128(nrow * 128 + c16 * 16));
            }
            #pragma unroll
            for (int mf = 0; mf < MF; mf++)
                #pragma unroll
                for (int ng = 0; ng < NG; ng++) {
                    MMA16816(acc[mf][ng * 2 + 0], ra[mf], rb[ng][0], rb[ng][1]);
                    MMA16816(acc[mf][ng * 2 + 1], ra[mf], rb[ng][2], rb[ng][3]);
                }
        }
    }

    const float al = g.alpha;

    if (CAUSAL == 0 && g.Vt) {
        __nv_bfloat16 (*st)[136] = (__nv_bfloat16 (*)[136])dsm;
        __syncthreads();
        #pragma unroll
        for (int mf = 0; mf < MF; mf++) {
            const int r_l = warpM * WTM + mf * 16 + (lane >> 2);
            #pragma unroll
            for (int nf = 0; nf < NG * 2; nf++) {
                const int c_l = warpN * WTN + nf * 8 + (lane & 3) * 2;
                st[c_l][r_l]         = __float2bfloat16(acc[mf][nf][0]);
                st[c_l + 1][r_l]     = __float2bfloat16(acc[mf][nf][1]);
                st[c_l][r_l + 8]     = __float2bfloat16(acc[mf][nf][2]);
                st[c_l + 1][r_l + 8] = __float2bfloat16(acc[mf][nf][3]);
            }
        }
        __syncthreads();
        const int rb_ = by >> 3;
        const int s0 = (by & 7) * 128;
        const int d = tid >> 1;
        const int so = (tid & 1) * 64;
        const uint4* src = (const uint4*)&st[d][so];
        uint4* dst = (uint4*)(g.Vt + (long long)rb_ * Dd * Ss
                              + (long long)(bx * BNp + d) * Ss + s0 + so);
        #pragma unroll
        for (int i = 0; i < 8; i++) dst[i] = src[i];
        return;
    }

    __nv_bfloat16* Cb = (CAUSAL == 0) ? (bz == 0 ? g.Cb0 : g.Cb1) : nullptr;
    float* Cf = g.Cf;
    #pragma unroll
    for (int mf = 0; mf < MF; mf++) {
        const long long r0 = (long long)(by * BMp + warpM * WTM + mf * 16 + (lane >> 2));
        const long long r1 = r0 + 8;
        #pragma unroll
        for (int nf = 0; nf < NG * 2; nf++) {
            const int c0 = bx * BNp + warpN * WTN + nf * 8 + (lane & 3) * 2;
            float v00 = acc[mf][nf][0] * al, v01 = acc[mf][nf][1] * al;
            float v10 = acc[mf][nf][2] * al, v11 = acc[mf][nf][3] * al;
            if (CAUSAL == 0) {
                __nv_bfloat162 p0, p1;
                p0.x = __float2bfloat16(v00); p0.y = __float2bfloat16(v01);
                p1.x = __float2bfloat16(v10); p1.y = __float2bfloat16(v11);
                *(__nv_bfloat162*)(Cb + bz * g.sC + r0 * g.N + c0) = p0;
                *(__nv_bfloat162*)(Cb + bz * g.sC + r1 * g.N + c0) = p1;
            } else {
                *(float2*)(Cf + bz * g.sC + r0 * g.N + c0) = make_float2(v00, v01);
                *(float2*)(Cf + bz * g.sC + r1 * g.N + c0) = make_float2(v10, v11);
            }
        }
    }
}

constexpr int SM_QK  = (128 + 128) * 128 * 3;   // 98304, 2 CTA/SM
constexpr int SM_V   = (128 + 128) * 128 * 5;   // 163840, 1 CTA/SM
constexpr int SM_SC  = (128 + 64) * 128 * 5;    // 122880, 1 CTA/SM
constexpr int SM_PV  = (64 + 128) * 128 * 3;    // 73728, 2 CTA/SM

// ---------------- elementwise bf16 cast ----------------
__global__ __launch_bounds__(256)
void splitH_kernel(const float* __restrict__ in, __nv_bfloat16* __restrict__ h, int n)
{
    int i = blockIdx.x * 256 + threadIdx.x;
    if (i < n) h[i] = __float2bfloat16(in[i]);
}

// merged 3-weight transpose
struct TW3 { const float *i0, *i1, *i2; __nv_bfloat16 *h0, *h1, *h2; };
__global__ __launch_bounds__(256)
void transpose_w3(TW3 a)
{
    const int z = blockIdx.z;
    const float* in = (z == 0 ? a.i0 : z == 1 ? a.i1 : a.i2);
    __nv_bfloat16* oh = (z == 0 ? a.h0 : z == 1 ? a.h1 : a.h2);
    __shared__ float t[32][33];
    const int c0 = blockIdx.x * 32, r0 = blockIdx.y * 32;
    const int x = threadIdx.x & 31, y = threadIdx.x >> 5;
    #pragma unroll
    for (int r = y; r < 32; r += 8) t[r][x] = in[(long long)(r0 + r) * Dd + c0 + x];
    __syncthreads();
    #pragma unroll
    for (int r = y; r < 32; r += 8)
        oh[(long long)(c0 + r) * Dd + r0 + x] = __float2bfloat16(t[x][r]);
}

// ---------------- positions + splat influence: 4 tokens / 256 threads ----------------
__global__ __launch_bounds__(256)
void pos_influence_kernel(const float* __restrict__ x, const float* __restrict__ posW,
                          const float* __restrict__ posB, const float* __restrict__ posBias,
                          const float* __restrict__ splatPos, const float* __restrict__ logScales,
                          float* __restrict__ wout)
{
    const int t0 = blockIdx.x * 4;
    const int b = t0 >> 10;
    const int s0 = t0 & 1023;
    __shared__ float xs[4][Dd];
    __shared__ float pos[4][Ee];
    const int tid = threadIdx.x;
    const int e = tid & 63, tg = tid >> 6;
    for (int i = tid; i < 4 * Dd; i += 256)
        xs[i >> 10][i & 1023] = x[(long long)t0 * Dd + i];
    __syncthreads();
    float acc = posB[e];
    const float* xr = xs[tg];
    #pragma unroll 8
    for (int d = 0; d < Dd; d++) acc += xr[d] * __ldg(&posW[d * Ee + e]);
    pos[tg][e] = tanhf(acc) + posBias[(s0 + tg) * Ee + e];
    __syncthreads();
    if (tid < 64) {
        const int n = tid & 15, tk = tid >> 4;
        float sc = expf(logScales[n]);
        sc = fminf(fmaxf(sc, 0.3f), 2.0f);
        float dsq = 0.0f;
        #pragma unroll
        for (int j = 0; j < Ee; j++) {
            float d = pos[tk][j] - splatPos[n * Ee + j];
            dsq += d * d;
        }
        float inf = fmaxf(__expf(-0.5f * dsq / (sc * sc)), 0.01f);
        wout[((long long)b * Nn + n) * Ss + s0 + tk] = inf;
    }
}

// ---------------- aggregated softmax -> P̄: warp-per-row, w in smem, exp recompute ----------------
// grid (Ss/8, Bb), 256 threads = 8 warps = 8 rows. Dyn smem: w[Nn][Ss] of this batch (64KB).
#define PB_SMEM (Nn * Ss * 4)
__global__ __launch_bounds__(256)
void pbar_kernel(const float* __restrict__ Abuf, const float* __restrict__ wbuf,
                 const float* __restrict__ gates, __nv_bfloat16* __restrict__ Phi)
{
    extern __shared__ float ws[];                 // [Nn][Ss]
    const int b = blockIdx.y;
    const int tid = threadIdx.x, wid = tid >> 5, lane = tid & 31;
    const float* wsrc = wbuf + (long long)b * Nn * Ss;
    for (int idx = tid; idx < (Nn * Ss) / 4; idx += 256)
        ((float4*)ws)[idx] = ((const float4*)wsrc)[idx];
    __syncthreads();

    const int i = blockIdx.x * 8 + wid;
    const int len = i + 1;
    const int nc = (len + 31) >> 5;               // active 32-chunks
    const float* Arow = Abuf + ((long long)b << 20) + ((long long)i << 10);

    float aL[32], accL[32];
    #pragma unroll 1
    for (int c = 0; c < nc; c++) {
        int j = lane + (c << 5);
        aL[c] = (j < len) ? Arow[j] : 0.0f;
        accL[c] = 0.0f;
    }
    #pragma unroll 1
    for (int n = 0; n < Nn; n++) {
        const float* wr = ws + (n << 10);
        const float wi = wr[i];
        float s = 0.0f;
        #pragma unroll 1
        for (int c = 0; c < nc; c++) {
            int j = lane + (c << 5);
            float e = (j < len) ? __expf(wi * wr[j] * aL[c]) : 0.0f;
            s += e;
        }
        s = warpSum(s);
        const float gsc = (1.0f / (1.0f + __expf(-gates[n]))) / (16.0f * s);
        #pragma unroll 1
        for (int c = 0; c < nc; c++) {
            int j = lane + (c << 5);
            if (j < len) accL[c] += gsc * __expf(wi * wr[j] * aL[c]);
        }
    }
    // write zeros out to the 64-row PV tile boundary (PV's K-truncation reads up to there)
    const int kEnd = ((i >> 6) + 1) << 6;
    __nv_bfloat16* ph = Phi + ((long long)b << 20) + ((long long)i << 10);
    #pragma unroll 1
    for (int c = 0; c < (kEnd >> 5); c++) {
        int j = lane + (c << 5);
        ph[j] = __float2bfloat16((j < len && c < nc) ? accL[c] : 0.0f);
    }
}

// ---------------- residual + LayerNorm ----------------
__global__ __launch_bounds__(256)
void final_ln_kernel(const float* __restrict__ x, const float* __restrict__ comb,
                     const float* __restrict__ rwp, const float* __restrict__ lnw,
                     const float* __restrict__ lnb, float* __restrict__ out)
{
    const int row = blockIdx.x;
    const int tid = threadIdx.x;
    __shared__ float red[9];
    const float rw = 1.0f / (1.0f + expf(-rwp[0]));
    const float om = 1.0f - rw;
    const float4 xv = ((const float4*)(x + (long long)row * Dd))[tid];
    const float4 cv = ((const float4*)(comb + (long long)row * Dd))[tid];
    float o0 = rw * xv.x + om * cv.x;
    float o1 = rw * xv.y + om * cv.y;
    float o2 = rw * xv.z + om * cv.z;
    float o3 = rw * xv.w + om * cv.w;
    float s = o0 + o1 + o2 + o3;
    float sq = o0 * o0 + o1 * o1 + o2 * o2 + o3 * o3;
    s = blockSum(s, red);
    __syncthreads();
    sq = blockSum(sq, red);
    const float mean = s * (1.0f / Dd);
    const float var = sq * (1.0f / Dd) - mean * mean;
    const float rstd = rsqrtf(var + 1e-5f);
    const float4 wv = ((const float4*)lnw)[tid];
    const float4 bv = ((const float4*)lnb)[tid];
    float4 ov;
    ov.x = (o0 - mean) * rstd * wv.x + bv.x;
    ov.y = (o1 - mean) * rstd * wv.y + bv.y;
    ov.z = (o2 - mean) * rstd * wv.z + bv.z;
    ov.w = (o3 - mean) * rstd * wv.w + bv.w;
    ((float4*)(out + (long long)row * Dd))[tid] = ov;
}

// ---------------- host launcher ----------------
static cudaStream_t g_s1, g_s2;
static cudaEvent_t g_evF1, g_evF2, g_evX, g_evJ1, g_evJ2, g_evV;

extern "C" void kernel_launch(void* const* d_in, const int* in_sizes, int n_in,
                              void* d_out, int out_size)
{
    const float* x        = (const float*)d_in[0];
    const float* posW     = (const float*)d_in[1];
    const float* posB     = (const float*)d_in[2];
    const float* posBias  = (const float*)d_in[3];
    const float* splatPos = (const float*)d_in[4];
    const float* logSc    = (const float*)d_in[5];
    const float* qW       = (const float*)d_in[6];
    const float* kW       = (const float*)d_in[7];
    const float* vW       = (const float*)d_in[8];
    const float* gates    = (const float*)d_in[9];
    const float* rwp      = (const float*)d_in[10];
    const float* lnw      = (const float*)d_in[11];
    const float* lnb      = (const float*)d_in[12];
    float* out = (float*)d_out;

    static bool inited = []() {
        cudaFuncSetAttribute((const void*)hmma_gemm<0, 128, 128, 4, 2, 3>,
                             cudaFuncAttributeMaxDynamicSharedMemorySize, SM_QK);
        cudaFuncSetAttribute((const void*)hmma_gemm<0, 128, 128, 4, 2, 5>,
                             cudaFuncAttributeMaxDynamicSharedMemorySize, SM_V);
        cudaFuncSetAttribute((const void*)hmma_gemm<1, 128, 64, 4, 2, 5>,
                             cudaFuncAttributeMaxDynamicSharedMemorySize, SM_SC);
        cudaFuncSetAttribute((const void*)hmma_gemm<2, 64, 128, 2, 4, 3>,
                             cudaFuncAttributeMaxDynamicSharedMemorySize, SM_PV);
        cudaFuncSetAttribute((const void*)pbar_kernel,
                             cudaFuncAttributeMaxDynamicSharedMemorySize, PB_SMEM);
        cudaStreamCreateWithFlags(&g_s1, cudaStreamNonBlocking);
        cudaStreamCreateWithFlags(&g_s2, cudaStreamNonBlocking);
        cudaEventCreateWithFlags(&g_evF1, cudaEventDisableTiming);
        cudaEventCreateWithFlags(&g_evF2, cudaEventDisableTiming);
        cudaEventCreateWithFlags(&g_evX, cudaEventDisableTiming);
        cudaEventCreateWithFlags(&g_evJ1, cudaEventDisableTiming);
        cudaEventCreateWithFlags(&g_evJ2, cudaEventDisableTiming);
        cudaEventCreateWithFlags(&g_evV, cudaEventDisableTiming);
        return true;
    }();
    (void)inited;

    float *A, *comb, *w;
    __nv_bfloat16 *xh, *wqh, *wkh, *wvh, *Qh, *Kh, *Vth, *Ph;
    cudaGetSymbolAddress((void**)&A, g_A);
    cudaGetSymbolAddress((void**)&comb, g_comb);
    cudaGetSymbolAddress((void**)&w, g_w);
    cudaGetSymbolAddress((void**)&xh, g_xh);
    cudaGetSymbolAddress((void**)&wqh, g_wqh);
    cudaGetSymbolAddress((void**)&wkh, g_wkh);
    cudaGetSymbolAddress((void**)&wvh, g_wvh);
    cudaGetSymbolAddress((void**)&Qh, g_Qh);
    cudaGetSymbolAddress((void**)&Kh, g_Kh);
    cudaGetSymbolAddress((void**)&Vth, g_Vth);
    cudaGetSymbolAddress((void**)&Ph, g_Ph);

    const float inv_sqrt_d = 1.0f / 32.0f;

    // fork: pos_influence on s1 (joins before pbar)
    cudaEventRecord(g_evF1, 0);
    cudaStreamWaitEvent(g_s1, g_evF1, 0);
    pos_influence_kernel<<<Mtot / 4, 256, 0, g_s1>>>(x, posW, posB, posBias, splatPos, logSc, w);
    cudaEventRecord(g_evJ1, g_s1);

    // fork: weight transpose on s2
    cudaEventRecord(g_evF2, 0);
    cudaStreamWaitEvent(g_s2, g_evF2, 0);
    {
        TW3 tw = { qW, kW, vW, wqh, wkh, wvh };
        transpose_w3<<<dim3(32, 32, 3), 256, 0, g_s2>>>(tw);
    }
    cudaEventRecord(g_evJ2, g_s2);

    // main: x -> bf16
    splitH_kernel<<<(Mtot * Dd) / 256, 256>>>(x, xh, Mtot * Dd);
    cudaEventRecord(g_evX, 0);

    // V projection on s2 (needs xh + wvh); deep pipeline, off critical path
    cudaStreamWaitEvent(g_s2, g_evX, 0);
    {
        GemmArgs a = {};
        a.A = xh; a.sA = 0;
        a.B0 = wvh; a.B1 = wvh; a.B2 = wvh; a.sB = 0;
        a.Vt = Vth; a.sC = 0;
        a.M = Mtot; a.N = Dd; a.K = Dd; a.alpha = 1.0f;
        hmma_gemm<0, 128, 128, 4, 2, 5><<<dim3(Dd / 128, Mtot / 128, 1), 256, SM_V, g_s2>>>(a);
    }
    cudaEventRecord(g_evV, g_s2);

    // main: Q,K projections
    cudaStreamWaitEvent(0, g_evJ2, 0);
    {
        GemmArgs a = {};
        a.A = xh; a.sA = 0;
        a.B0 = wqh; a.B1 = wkh; a.B2 = wkh; a.sB = 0;
        a.Cb0 = Qh; a.Cb1 = Kh; a.sC = 0;
        a.M = Mtot; a.N = Dd; a.K = Dd; a.alpha = 1.0f;
        hmma_gemm<0, 128, 128, 4, 2, 3><<<dim3(Dd / 128, Mtot / 128, 2), 256, SM_QK>>>(a);
    }
    // scores A = Q K^T / sqrt(d), 128x64 tiles, lower-tri only, deep pipeline
    {
        GemmArgs a = {};
        a.A = Qh; a.sA = (long long)Ss * Dd;
        a.B0 = Kh; a.B1 = Kh; a.B2 = Kh; a.sB = (long long)Ss * Dd;
        a.Cf = A; a.sC = (long long)Ss * Ss;
        a.M = Ss; a.N = Ss; a.K = Dd; a.alpha = inv_sqrt_d;
        hmma_gemm<1, 128, 64, 4, 2, 5><<<dim3(Ss / 64, Ss / 128, Bb), 256, SM_SC>>>(a);
    }
    // join influence -> pbar (warp-per-row, w staged in smem)
    cudaStreamWaitEvent(0, g_evJ1, 0);
    pbar_kernel<<<dim3(Ss / 8, Bb), 256, PB_SMEM>>>(A, w, gates, Ph);
    // join V -> PV: comb = P̄ @ V, 64x128 tiles, K-truncated
    cudaStreamWaitEvent(0, g_evV, 0);
    {
        GemmArgs a = {};
        a.A = Ph; a.sA = (long long)Ss * Ss;
        a.B0 = Vth; a.B1 = Vth; a.B2 = Vth; a.sB = (long long)Dd * Ss;
        a.Cf = comb; a.sC = (long long)Ss * Dd;
        a.M = Ss; a.N = Dd; a.K = Ss; a.alpha = 1.0f;
        hmma_gemm<2, 64, 128, 2, 4, 3><<<dim3(Dd / 128, Ss / 64, Bb), 256, SM_PV>>>(a);
    }
    // residual + LayerNorm
    final_ln_kernel<<<Mtot, 256>>>(x, comb, rwp, lnw, lnb, out);
}

// round 15
// speedup vs baseline: 2.2644x; 2.2644x over previous
#include <cuda_runtime.h>
#include <cuda_bf16.h>
#include <math.h>
#include <stdint.h>

#define Bb 2
#define Ss 1024
#define Dd 1024
#define Ee 64
#define Nn 16
#define Mtot (Bb * Ss)

// ---------------- scratch (no allocation allowed) ----------------
__device__ float g_A[Bb * Ss * Ss];        // QK^T/sqrt(d) fp32
__device__ float g_comb[Bb * Ss * Dd];
__device__ float g_w[Bb * Nn * Ss];
__device__ __nv_bfloat16 g_xh[Mtot * Dd];
__device__ __nv_bfloat16 g_wqh[Dd * Dd];
__device__ __nv_bfloat16 g_wkh[Dd * Dd];
__device__ __nv_bfloat16 g_wvh[Dd * Dd];
__device__ __nv_bfloat16 g_Qh[Mtot * Dd];
__device__ __nv_bfloat16 g_Kh[Mtot * Dd];
__device__ __nv_bfloat16 g_Vth[Bb * Dd * Ss];   // V^T bf16, [b][d][s]
__device__ __nv_bfloat16 g_Ph[Bb * Ss * Ss];

// ---------------- helpers ----------------
__device__ __forceinline__ uint32_t smem_u32(const void* p) {
    uint32_t a;
    asm("{ .reg .u64 t; cvta.to.shared.u64 t, %1; cvt.u32.u64 %0, t; }" : "=r"(a) : "l"(p));
    return a;
}
__device__ __forceinline__ uint32_t sw128(uint32_t off) { return off ^ ((off >> 3) & 0x70); }

#define CP_ASYNC16(s, g) \
    asm volatile("cp.async.cg.shared.global [%0], [%1], 16;" :: "r"(s), "l"(g) : "memory")
#define CP_COMMIT() asm volatile("cp.async.commit_group;" ::: "memory")
template <int N>
__device__ __forceinline__ void cp_wait() {
    asm volatile("cp.async.wait_group %0;" :: "n"(N) : "memory");
}

#define LDSM_X4(r0, r1, r2, r3, addr) \
    asm volatile("ldmatrix.sync.aligned.m8n8.x4.shared.b16 {%0,%1,%2,%3}, [%4];" \
        : "=r"(r0), "=r"(r1), "=r"(r2), "=r"(r3) : "r"(addr) : "memory")

#define MMA16816(ac, a, b0, b1) \
    asm volatile("mma.sync.aligned.m16n8k16.row.col.f32.bf16.bf16.f32 " \
        "{%0,%1,%2,%3}, {%4,%5,%6,%7}, {%8,%9}, {%0,%1,%2,%3};" \
        : "+f"((ac)[0]), "+f"((ac)[1]), "+f"((ac)[2]), "+f"((ac)[3]) \
        : "r"((a)[0]), "r"((a)[1]), "r"((a)[2]), "r"((a)[3]), "r"(b0), "r"(b1))

// ---------------- reductions ----------------
__device__ __forceinline__ float warpSum(float v) {
    #pragma unroll
    for (int o = 16; o; o >>= 1) v += __shfl_xor_sync(0xffffffffu, v, o);
    return v;
}
__device__ __forceinline__ float blockSum(float v, float* red) {
    int lane = threadIdx.x & 31, w = threadIdx.x >> 5;
    v = warpSum(v);
    if (lane == 0) red[w] = v;
    __syncthreads();
    if (w == 0) {
        float t = (lane < 8) ? red[lane] : 0.0f;
        t = warpSum(t);
        if (lane == 0) red[8] = t;
    }
    __syncthreads();
    return red[8];
}

// ---------------- single-pass bf16 HMMA GEMM (round-12 champion config) ----------------
#define BKC 64

struct GemmArgs {
    const __nv_bfloat16* A; long long sA;
    const __nv_bfloat16 *B0, *B1, *B2; long long sB;
    float* Cf;
    __nv_bfloat16 *Cb0, *Cb1;
    __nv_bfloat16* Vt;
    long long sC;
    int M, N, K; float alpha;
};

// CAUSAL: 0=proj (Vt? transposed epilogue), 1=score (skip upper tiles), 2=PV (K-truncate)
template <int CAUSAL, int BMp, int BNp, int WM, int WN, int NST>
__global__ __launch_bounds__(256)
void hmma_gemm(GemmArgs g)
{
    constexpr int STG_A = BMp * 128;
    constexpr int STG_B = BNp * 128;
    constexpr int WTM = BMp / WM;
    constexpr int WTN = BNp / WN;
    constexpr int MF = WTM / 16;
    constexpr int NG = WTN / 16;
    constexpr int INFLT = NST - 1;

    const int bx = blockIdx.x, by = blockIdx.y, bz = blockIdx.z;
    if (CAUSAL == 1 && bx * BNp >= (by + 1) * BMp) return;
    int kEnd = g.K;
    if (CAUSAL == 2) kEnd = min(g.K, (by + 1) * BMp);
    const int NC = kEnd / BKC;

    extern __shared__ __align__(128) char dsm[];
    const uint32_t sAb = smem_u32(dsm);
    const uint32_t sBb = sAb + NST * STG_A;

    const int tid = threadIdx.x, wid = tid >> 5, lane = tid & 31;
    const int warpM = wid / WN, warpN = wid % WN;

    const __nv_bfloat16* Ah = g.A + bz * g.sA;
    const __nv_bfloat16* Bh = (bz == 0 ? g.B0 : bz == 1 ? g.B1 : g.B2) + bz * g.sB;

    float acc[MF][NG * 2][4];
    #pragma unroll
    for (int i = 0; i < MF; i++)
        #pragma unroll
        for (int j = 0; j < NG * 2; j++)
            #pragma unroll
            for (int k = 0; k < 4; k++) acc[i][j][k] = 0.0f;

    const int lc16 = tid & 7;
    const int lrow = tid >> 3;

    const __nv_bfloat16* Arow = Ah + (long long)(by * BMp) * g.K;
    const __nv_bfloat16* Brow = Bh + (long long)(bx * BNp) * g.K;
    const int Kld = g.K;

    auto issue = [&](int it, int buf) {
        const int k0 = it * BKC;
        const uint32_t aB = sAb + buf * STG_A;
        const uint32_t bB = sBb + buf * STG_B;
        #pragma unroll
        for (int r = 0; r < BMp / 32; r++) {
            const int row = lrow + 32 * r;
            CP_ASYNC16(aB + sw128(row * 128 + lc16 * 16),
                       Arow + (long long)row * Kld + k0 + lc16 * 8);
        }
        #pragma unroll
        for (int r = 0; r < BNp / 32; r++) {
            const int row = lrow + 32 * r;
            CP_ASYNC16(bB + sw128(row * 128 + lc16 * 16),
                       Brow + (long long)row * Kld + k0 + lc16 * 8);
        }
    };

    #pragma unroll
    for (int it = 0; it < INFLT; it++) {
        if (it < NC) issue(it, it);
        CP_COMMIT();
    }

    const int aRowL = (lane & 15);
    const int aHiK  = (lane >> 4);
    const int bRowL = ((lane & 16) >> 1) + (lane & 7);
    const int bHiK  = ((lane >> 3) & 1);

    #pragma unroll 1
    for (int it = 0; it < NC; it++) {
        cp_wait<NST - 2>();
        __syncthreads();
        const int nx = it + INFLT;
        if (nx < NC) issue(nx, nx % NST);
        CP_COMMIT();
        const int buf = it % NST;
        const uint32_t aB = sAb + buf * STG_A;
        const uint32_t bB = sBb + buf * STG_B;
        #pragma unroll
        for (int s = 0; s < 4; s++) {
            uint32_t ra[MF][4], rb[NG][4];
            #pragma unroll
            for (int mf = 0; mf < MF; mf++) {
                int row = warpM * WTM + mf * 16 + aRowL;
                int c16 = s * 2 + aHiK;
                LDSM_X4(ra[mf][0], ra[mf][1], ra[mf][2], ra[mf][3],
                        aB + sw128(row * 128 + c16 * 16));
            }
            #pragma unroll
            for (int ng = 0; ng < NG; ng++) {
                int nrow = warpN * WTN + ng * 16 + bRowL;
                int c16 = s * 2 + bHiK;
                LDSM_X4(rb[ng][0], rb[ng][1], rb[ng][2], rb[ng][3],
                        bB + sw128(nrow * 128 + c16 * 16));
            }
            #pragma unroll
            for (int mf = 0; mf < MF; mf++)
                #pragma unroll
                for (int ng = 0; ng < NG; ng++) {
                    MMA16816(acc[mf][ng * 2 + 0], ra[mf], rb[ng][0], rb[ng][1]);
                    MMA16816(acc[mf][ng * 2 + 1], ra[mf], rb[ng][2], rb[ng][3]);
                }
        }
    }

    const float al = g.alpha;

    if (CAUSAL == 0 && g.Vt) {
        __nv_bfloat16 (*st)[136] = (__nv_bfloat16 (*)[136])dsm;
        __syncthreads();
        #pragma unroll
        for (int mf = 0; mf < MF; mf++) {
            const int r_l = warpM * WTM + mf * 16 + (lane >> 2);
            #pragma unroll
            for (int nf = 0; nf < NG * 2; nf++) {
                const int c_l = warpN * WTN + nf * 8 + (lane & 3) * 2;
                st[c_l][r_l]         = __float2bfloat16(acc[mf][nf][0]);
                st[c_l + 1][r_l]     = __float2bfloat16(acc[mf][nf][1]);
                st[c_l][r_l + 8]     = __float2bfloat16(acc[mf][nf][2]);
                st[c_l + 1][r_l + 8] = __float2bfloat16(acc[mf][nf][3]);
            }
        }
        __syncthreads();
        const int rb_ = by >> 3;
        const int s0 = (by & 7) * 128;
        const int d = tid >> 1;
        const int so = (tid & 1) * 64;
        const uint4* src = (const uint4*)&st[d][so];
        uint4* dst = (uint4*)(g.Vt + (long long)rb_ * Dd * Ss
                              + (long long)(bx * BNp + d) * Ss + s0 + so);
        #pragma unroll
        for (int i = 0; i < 8; i++) dst[i] = src[i];
        return;
    }

    __nv_bfloat16* Cb = (CAUSAL == 0) ? (bz == 0 ? g.Cb0 : g.Cb1) : nullptr;
    float* Cf = g.Cf;
    #pragma unroll
    for (int mf = 0; mf < MF; mf++) {
        const long long r0 = (long long)(by * BMp + warpM * WTM + mf * 16 + (lane >> 2));
        const long long r1 = r0 + 8;
        #pragma unroll
        for (int nf = 0; nf < NG * 2; nf++) {
            const int c0 = bx * BNp + warpN * WTN + nf * 8 + (lane & 3) * 2;
            float v00 = acc[mf][nf][0] * al, v01 = acc[mf][nf][1] * al;
            float v10 = acc[mf][nf][2] * al, v11 = acc[mf][nf][3] * al;
            if (CAUSAL == 0) {
                __nv_bfloat162 p0, p1;
                p0.x = __float2bfloat16(v00); p0.y = __float2bfloat16(v01);
                p1.x = __float2bfloat16(v10); p1.y = __float2bfloat16(v11);
                *(__nv_bfloat162*)(Cb + bz * g.sC + r0 * g.N + c0) = p0;
                *(__nv_bfloat162*)(Cb + bz * g.sC + r1 * g.N + c0) = p1;
            } else {
                *(float2*)(Cf + bz * g.sC + r0 * g.N + c0) = make_float2(v00, v01);
                *(float2*)(Cf + bz * g.sC + r1 * g.N + c0) = make_float2(v10, v11);
            }
        }
    }
}

constexpr int SM_QK  = (128 + 128) * 128 * 3;   // 98304, 2 CTA/SM
constexpr int SM_V   = (128 + 128) * 128 * 5;   // 163840, 1 CTA/SM
constexpr int SM_SC  = (128 + 64) * 128 * 5;    // 122880, 1 CTA/SM
constexpr int SM_PV  = (64 + 128) * 128 * 3;    // 73728, 2 CTA/SM

// ---------------- elementwise bf16 cast ----------------
__global__ __launch_bounds__(256)
void splitH_kernel(const float* __restrict__ in, __nv_bfloat16* __restrict__ h, int n)
{
    int i = blockIdx.x * 256 + threadIdx.x;
    if (i < n) h[i] = __float2bfloat16(in[i]);
}

// merged 3-weight transpose
struct TW3 { const float *i0, *i1, *i2; __nv_bfloat16 *h0, *h1, *h2; };
__global__ __launch_bounds__(256)
void transpose_w3(TW3 a)
{
    const int z = blockIdx.z;
    const float* in = (z == 0 ? a.i0 : z == 1 ? a.i1 : a.i2);
    __nv_bfloat16* oh = (z == 0 ? a.h0 : z == 1 ? a.h1 : a.h2);
    __shared__ float t[32][33];
    const int c0 = blockIdx.x * 32, r0 = blockIdx.y * 32;
    const int x = threadIdx.x & 31, y = threadIdx.x >> 5;
    #pragma unroll
    for (int r = y; r < 32; r += 8) t[r][x] = in[(long long)(r0 + r) * Dd + c0 + x];
    __syncthreads();
    #pragma unroll
    for (int r = y; r < 32; r += 8)
        oh[(long long)(c0 + r) * Dd + r0 + x] = __float2bfloat16(t[x][r]);
}

// ---------------- positions + splat influence: 4 tokens / 256 threads ----------------
__global__ __launch_bounds__(256)
void pos_influence_kernel(const float* __restrict__ x, const float* __restrict__ posW,
                          const float* __restrict__ posB, const float* __restrict__ posBias,
                          const float* __restrict__ splatPos, const float* __restrict__ logScales,
                          float* __restrict__ wout)
{
    const int t0 = blockIdx.x * 4;
    const int b = t0 >> 10;
    const int s0 = t0 & 1023;
    __shared__ float xs[4][Dd];
    __shared__ float pos[4][Ee];
    const int tid = threadIdx.x;
    const int e = tid & 63, tg = tid >> 6;
    for (int i = tid; i < 4 * Dd; i += 256)
        xs[i >> 10][i & 1023] = x[(long long)t0 * Dd + i];
    __syncthreads();
    float acc = posB[e];
    const float* xr = xs[tg];
    #pragma unroll 8
    for (int d = 0; d < Dd; d++) acc += xr[d] * __ldg(&posW[d * Ee + e]);
    pos[tg][e] = tanhf(acc) + posBias[(s0 + tg) * Ee + e];
    __syncthreads();
    if (tid < 64) {
        const int n = tid & 15, tk = tid >> 4;
        float sc = expf(logScales[n]);
        sc = fminf(fmaxf(sc, 0.3f), 2.0f);
        float dsq = 0.0f;
        #pragma unroll
        for (int j = 0; j < Ee; j++) {
            float d = pos[tk][j] - splatPos[n * Ee + j];
            dsq += d * d;
        }
        float inf = fmaxf(__expf(-0.5f * dsq / (sc * sc)), 0.01f);
        wout[((long long)b * Nn + n) * Ss + s0 + tk] = inf;
    }
}

// ---------------- aggregated softmax -> P̄ (bf16), block-per-row ----------------
// Single exp pass: e stored bf16 in smem, all 16 sums reduced with ONE combined
// reduction (2 barriers total), then scaled accumulation from smem.
__global__ __launch_bounds__(256)
void pbar_kernel(const float* __restrict__ Abuf, const float* __restrict__ wbuf,
                 const float* __restrict__ gates, __nv_bfloat16* __restrict__ Phi)
{
    __shared__ __nv_bfloat16 sE[Nn][Ss];     // 32KB
    __shared__ float red[8][Nn];
    __shared__ float gscS[Nn];
    const int row = blockIdx.x;
    const int b = row >> 10, i = row & 1023;
    const float* Arow = Abuf + ((long long)b << 20) + ((long long)i << 10);
    const int tid = threadIdx.x, lane = tid & 31, wd = tid >> 5;
    const int len = i + 1;

    float aL[4];
    #pragma unroll
    for (int k = 0; k < 4; k++) {
        int j = tid + k * 256;
        aL[k] = (j < len) ? Arow[j] : 0.0f;
    }

    float s[Nn];
    #pragma unroll
    for (int n = 0; n < Nn; n++) {
        const float* wrow = wbuf + (((long long)b * Nn + n) << 10);
        const float wi = wrow[i];
        float sn = 0.0f;
        #pragma unroll
        for (int k = 0; k < 4; k++) {
            int j = tid + k * 256;
            float e = 0.0f;
            if (j < len) e = __expf(wi * wrow[j] * aL[k]);
            sE[n][j] = __float2bfloat16(e);
            sn += e;
        }
        s[n] = sn;
    }
    // combined reduction of 16 sums: warp shuffles -> 8x16 smem -> 16 threads
    #pragma unroll
    for (int n = 0; n < Nn; n++) s[n] = warpSum(s[n]);
    if (lane == 0) {
        #pragma unroll
        for (int n = 0; n < Nn; n++) red[wd][n] = s[n];
    }
    __syncthreads();
    if (tid < Nn) {
        float t = 0.0f;
        #pragma unroll
        for (int ww = 0; ww < 8; ww++) t += red[ww][tid];
        gscS[tid] = (1.0f / (1.0f + __expf(-gates[tid]))) / (16.0f * t);
    }
    __syncthreads();

    float accL[4] = {0, 0, 0, 0};
    #pragma unroll
    for (int n = 0; n < Nn; n++) {
        const float gsc = gscS[n];
        #pragma unroll
        for (int k = 0; k < 4; k++) {
            int j = tid + k * 256;
            accL[k] += gsc * __bfloat162float(sE[n][j]);
        }
    }
    __nv_bfloat16* ph = Phi + ((long long)b << 20) + ((long long)i << 10);
    #pragma unroll
    for (int k = 0; k < 4; k++) {
        int j = tid + k * 256;
        ph[j] = __float2bfloat16(accL[k]);
    }
}

// ---------------- residual + LayerNorm ----------------
__global__ __launch_bounds__(256)
void final_ln_kernel(const float* __restrict__ x, const float* __restrict__ comb,
                     const float* __restrict__ rwp, const float* __restrict__ lnw,
                     const float* __restrict__ lnb, float* __restrict__ out)
{
    const int row = blockIdx.x;
    const int tid = threadIdx.x;
    __shared__ float red[9];
    const float rw = 1.0f / (1.0f + expf(-rwp[0]));
    const float om = 1.0f - rw;
    const float4 xv = ((const float4*)(x + (long long)row * Dd))[tid];
    const float4 cv = ((const float4*)(comb + (long long)row * Dd))[tid];
    float o0 = rw * xv.x + om * cv.x;
    float o1 = rw * xv.y + om * cv.y;
    float o2 = rw * xv.z + om * cv.z;
    float o3 = rw * xv.w + om * cv.w;
    float s = o0 + o1 + o2 + o3;
    float sq = o0 * o0 + o1 * o1 + o2 * o2 + o3 * o3;
    s = blockSum(s, red);
    __syncthreads();
    sq = blockSum(sq, red);
    const float mean = s * (1.0f / Dd);
    const float var = sq * (1.0f / Dd) - mean * mean;
    const float rstd = rsqrtf(var + 1e-5f);
    const float4 wv = ((const float4*)lnw)[tid];
    const float4 bv = ((const float4*)lnb)[tid];
    float4 ov;
    ov.x = (o0 - mean) * rstd * wv.x + bv.x;
    ov.y = (o1 - mean) * rstd * wv.y + bv.y;
    ov.z = (o2 - mean) * rstd * wv.z + bv.z;
    ov.w = (o3 - mean) * rstd * wv.w + bv.w;
    ((float4*)(out + (long long)row * Dd))[tid] = ov;
}

// ---------------- host launcher ----------------
static cudaStream_t g_s1, g_s2;
static cudaEvent_t g_evF1, g_evF2, g_evX, g_evJ1, g_evJ2, g_evV;

extern "C" void kernel_launch(void* const* d_in, const int* in_sizes, int n_in,
                              void* d_out, int out_size)
{
    const float* x        = (const float*)d_in[0];
    const float* posW     = (const float*)d_in[1];
    const float* posB     = (const float*)d_in[2];
    const float* posBias  = (const float*)d_in[3];
    const float* splatPos = (const float*)d_in[4];
    const float* logSc    = (const float*)d_in[5];
    const float* qW       = (const float*)d_in[6];
    const float* kW       = (const float*)d_in[7];
    const float* vW       = (const float*)d_in[8];
    const float* gates    = (const float*)d_in[9];
    const float* rwp      = (const float*)d_in[10];
    const float* lnw      = (const float*)d_in[11];
    const float* lnb      = (const float*)d_in[12];
    float* out = (float*)d_out;

    static bool inited = []() {
        cudaFuncSetAttribute((const void*)hmma_gemm<0, 128, 128, 4, 2, 3>,
                             cudaFuncAttributeMaxDynamicSharedMemorySize, SM_QK);
        cudaFuncSetAttribute((const void*)hmma_gemm<0, 128, 128, 4, 2, 5>,
                             cudaFuncAttributeMaxDynamicSharedMemorySize, SM_V);
        cudaFuncSetAttribute((const void*)hmma_gemm<1, 128, 64, 4, 2, 5>,
                             cudaFuncAttributeMaxDynamicSharedMemorySize, SM_SC);
        cudaFuncSetAttribute((const void*)hmma_gemm<2, 64, 128, 2, 4, 3>,
                             cudaFuncAttributeMaxDynamicSharedMemorySize, SM_PV);
        cudaStreamCreateWithFlags(&g_s1, cudaStreamNonBlocking);
        cudaStreamCreateWithFlags(&g_s2, cudaStreamNonBlocking);
        cudaEventCreateWithFlags(&g_evF1, cudaEventDisableTiming);
        cudaEventCreateWithFlags(&g_evF2, cudaEventDisableTiming);
        cudaEventCreateWithFlags(&g_evX, cudaEventDisableTiming);
        cudaEventCreateWithFlags(&g_evJ1, cudaEventDisableTiming);
        cudaEventCreateWithFlags(&g_evJ2, cudaEventDisableTiming);
        cudaEventCreateWithFlags(&g_evV, cudaEventDisableTiming);
        return true;
    }();
    (void)inited;

    float *A, *comb, *w;
    __nv_bfloat16 *xh, *wqh, *wkh, *wvh, *Qh, *Kh, *Vth, *Ph;
    cudaGetSymbolAddress((void**)&A, g_A);
    cudaGetSymbolAddress((void**)&comb, g_comb);
    cudaGetSymbolAddress((void**)&w, g_w);
    cudaGetSymbolAddress((void**)&xh, g_xh);
    cudaGetSymbolAddress((void**)&wqh, g_wqh);
    cudaGetSymbolAddress((void**)&wkh, g_wkh);
    cudaGetSymbolAddress((void**)&wvh, g_wvh);
    cudaGetSymbolAddress((void**)&Qh, g_Qh);
    cudaGetSymbolAddress((void**)&Kh, g_Kh);
    cudaGetSymbolAddress((void**)&Vth, g_Vth);
    cudaGetSymbolAddress((void**)&Ph, g_Ph);

    const float inv_sqrt_d = 1.0f / 32.0f;

    // fork: pos_influence on s1 (joins before pbar)
    cudaEventRecord(g_evF1, 0);
    cudaStreamWaitEvent(g_s1, g_evF1, 0);
    pos_influence_kernel<<<Mtot / 4, 256, 0, g_s1>>>(x, posW, posB, posBias, splatPos, logSc, w);
    cudaEventRecord(g_evJ1, g_s1);

    // fork: weight transpose on s2
    cudaEventRecord(g_evF2, 0);
    cudaStreamWaitEvent(g_s2, g_evF2, 0);
    {
        TW3 tw = { qW, kW, vW, wqh, wkh, wvh };
        transpose_w3<<<dim3(32, 32, 3), 256, 0, g_s2>>>(tw);
    }
    cudaEventRecord(g_evJ2, g_s2);

    // main: x -> bf16
    splitH_kernel<<<(Mtot * Dd) / 256, 256>>>(x, xh, Mtot * Dd);
    cudaEventRecord(g_evX, 0);

    // V projection on s2 (needs xh + wvh); deep pipeline, off critical path
    cudaStreamWaitEvent(g_s2, g_evX, 0);
    {
        GemmArgs a = {};
        a.A = xh; a.sA = 0;
        a.B0 = wvh; a.B1 = wvh; a.B2 = wvh; a.sB = 0;
        a.Vt = Vth; a.sC = 0;
        a.M = Mtot; a.N = Dd; a.K = Dd; a.alpha = 1.0f;
        hmma_gemm<0, 128, 128, 4, 2, 5><<<dim3(Dd / 128, Mtot / 128, 1), 256, SM_V, g_s2>>>(a);
    }
    cudaEventRecord(g_evV, g_s2);

    // main: Q,K projections
    cudaStreamWaitEvent(0, g_evJ2, 0);
    {
        GemmArgs a = {};
        a.A = xh; a.sA = 0;
        a.B0 = wqh; a.B1 = wkh; a.B2 = wkh; a.sB = 0;
        a.Cb0 = Qh; a.Cb1 = Kh; a.sC = 0;
        a.M = Mtot; a.N = Dd; a.K = Dd; a.alpha = 1.0f;
        hmma_gemm<0, 128, 128, 4, 2, 3><<<dim3(Dd / 128, Mtot / 128, 2), 256, SM_QK>>>(a);
    }
    // scores A = Q K^T / sqrt(d), 128x64 tiles, lower-tri only, deep pipeline
    {
        GemmArgs a = {};
        a.A = Qh; a.sA = (long long)Ss * Dd;
        a.B0 = Kh; a.B1 = Kh; a.B2 = Kh; a.sB = (long long)Ss * Dd;
        a.Cf = A; a.sC = (long long)Ss * Ss;
        a.M = Ss; a.N = Ss; a.K = Dd; a.alpha = inv_sqrt_d;
        hmma_gemm<1, 128, 64, 4, 2, 5><<<dim3(Ss / 64, Ss / 128, Bb), 256, SM_SC>>>(a);
    }
    // join influence -> pbar
    cudaStreamWaitEvent(0, g_evJ1, 0);
    pbar_kernel<<<Mtot, 256>>>(A, w, gates, Ph);
    // join V -> PV: comb = P̄ @ V, 64x128 tiles, K-truncated
    cudaStreamWaitEvent(0, g_evV, 0);
    {
        GemmArgs a = {};
        a.A = Ph; a.sA = (long long)Ss * Ss;
        a.B0 = Vth; a.B1 = Vth; a.B2 = Vth; a.sB = (long long)Dd * Ss;
        a.Cf = comb; a.sC = (long long)Ss * Dd;
        a.M = Ss; a.N = Dd; a.K = Ss; a.alpha = 1.0f;
        hmma_gemm<2, 64, 128, 2, 4, 3><<<dim3(Dd / 128, Ss / 64, Bb), 256, SM_PV>>>(a);
    }
    // residual + LayerNorm
    final_ln_kernel<<<Mtot, 256>>>(x, comb, rwp, lnw, lnb, out);
}

// round 16
// speedup vs baseline: 2.3221x; 1.0255x over previous
#include <cuda_runtime.h>
#include <cuda_bf16.h>
#include <math.h>
#include <stdint.h>

#define Bb 2
#define Ss 1024
#define Dd 1024
#define Ee 64
#define Nn 16
#define Mtot (Bb * Ss)

// ---------------- scratch (no allocation allowed) ----------------
__device__ float g_A[Bb * Ss * Ss];        // QK^T/sqrt(d) fp32
__device__ float g_comb[Bb * Ss * Dd];
__device__ float g_w[Bb * Nn * Ss];
__device__ __nv_bfloat16 g_xh[Mtot * Dd];
__device__ __nv_bfloat16 g_wqh[Dd * Dd];
__device__ __nv_bfloat16 g_wkh[Dd * Dd];
__device__ __nv_bfloat16 g_wvh[Dd * Dd];
__device__ __nv_bfloat16 g_Qh[Mtot * Dd];
__device__ __nv_bfloat16 g_Kh[Mtot * Dd];
__device__ __nv_bfloat16 g_Vth[Bb * Dd * Ss];   // V^T bf16, [b][d][s]
__device__ __nv_bfloat16 g_Ph[Bb * Ss * Ss];

// ---------------- helpers ----------------
__device__ __forceinline__ uint32_t smem_u32(const void* p) {
    uint32_t a;
    asm("{ .reg .u64 t; cvta.to.shared.u64 t, %1; cvt.u32.u64 %0, t; }" : "=r"(a) : "l"(p));
    return a;
}
__device__ __forceinline__ uint32_t sw128(uint32_t off) { return off ^ ((off >> 3) & 0x70); }

#define CP_ASYNC16(s, g) \
    asm volatile("cp.async.cg.shared.global [%0], [%1], 16;" :: "r"(s), "l"(g) : "memory")
#define CP_COMMIT() asm volatile("cp.async.commit_group;" ::: "memory")
template <int N>
__device__ __forceinline__ void cp_wait() {
    asm volatile("cp.async.wait_group %0;" :: "n"(N) : "memory");
}

#define LDSM_X4(r0, r1, r2, r3, addr) \
    asm volatile("ldmatrix.sync.aligned.m8n8.x4.shared.b16 {%0,%1,%2,%3}, [%4];" \
        : "=r"(r0), "=r"(r1), "=r"(r2), "=r"(r3) : "r"(addr) : "memory")

#define MMA16816(ac, a, b0, b1) \
    asm volatile("mma.sync.aligned.m16n8k16.row.col.f32.bf16.bf16.f32 " \
        "{%0,%1,%2,%3}, {%4,%5,%6,%7}, {%8,%9}, {%0,%1,%2,%3};" \
        : "+f"((ac)[0]), "+f"((ac)[1]), "+f"((ac)[2]), "+f"((ac)[3]) \
        : "r"((a)[0]), "r"((a)[1]), "r"((a)[2]), "r"((a)[3]), "r"(b0), "r"(b1))

// ---------------- reductions ----------------
__device__ __forceinline__ float warpSum(float v) {
    #pragma unroll
    for (int o = 16; o; o >>= 1) v += __shfl_xor_sync(0xffffffffu, v, o);
    return v;
}
__device__ __forceinline__ float blockSum(float v, float* red) {
    int lane = threadIdx.x & 31, w = threadIdx.x >> 5;
    v = warpSum(v);
    if (lane == 0) red[w] = v;
    __syncthreads();
    if (w == 0) {
        float t = (lane < 8) ? red[lane] : 0.0f;
        t = warpSum(t);
        if (lane == 0) red[8] = t;
    }
    __syncthreads();
    return red[8];
}

// ---------------- single-pass bf16 HMMA GEMM (round-12 champion config) ----------------
#define BKC 64

struct GemmArgs {
    const __nv_bfloat16* A; long long sA;
    const __nv_bfloat16 *B0, *B1, *B2; long long sB;
    float* Cf;
    __nv_bfloat16 *Cb0, *Cb1;
    __nv_bfloat16* Vt;
    long long sC;
    int M, N, K; float alpha;
};

// CAUSAL: 0=proj (Vt? transposed epilogue), 1=score (skip upper tiles), 2=PV (K-truncate)
template <int CAUSAL, int BMp, int BNp, int WM, int WN, int NST>
__global__ __launch_bounds__(256)
void hmma_gemm(GemmArgs g)
{
    constexpr int STG_A = BMp * 128;
    constexpr int STG_B = BNp * 128;
    constexpr int WTM = BMp / WM;
    constexpr int WTN = BNp / WN;
    constexpr int MF = WTM / 16;
    constexpr int NG = WTN / 16;
    constexpr int INFLT = NST - 1;

    const int bx = blockIdx.x, by = blockIdx.y, bz = blockIdx.z;
    if (CAUSAL == 1 && bx * BNp >= (by + 1) * BMp) return;
    int kEnd = g.K;
    if (CAUSAL == 2) kEnd = min(g.K, (by + 1) * BMp);
    const int NC = kEnd / BKC;

    extern __shared__ __align__(128) char dsm[];
    const uint32_t sAb = smem_u32(dsm);
    const uint32_t sBb = sAb + NST * STG_A;

    const int tid = threadIdx.x, wid = tid >> 5, lane = tid & 31;
    const int warpM = wid / WN, warpN = wid % WN;

    const __nv_bfloat16* Ah = g.A + bz * g.sA;
    const __nv_bfloat16* Bh = (bz == 0 ? g.B0 : bz == 1 ? g.B1 : g.B2) + bz * g.sB;

    float acc[MF][NG * 2][4];
    #pragma unroll
    for (int i = 0; i < MF; i++)
        #pragma unroll
        for (int j = 0; j < NG * 2; j++)
            #pragma unroll
            for (int k = 0; k < 4; k++) acc[i][j][k] = 0.0f;

    const int lc16 = tid & 7;
    const int lrow = tid >> 3;

    const __nv_bfloat16* Arow = Ah + (long long)(by * BMp) * g.K;
    const __nv_bfloat16* Brow = Bh + (long long)(bx * BNp) * g.K;
    const int Kld = g.K;

    auto issue = [&](int it, int buf) {
        const int k0 = it * BKC;
        const uint32_t aB = sAb + buf * STG_A;
        const uint32_t bB = sBb + buf * STG_B;
        #pragma unroll
        for (int r = 0; r < BMp / 32; r++) {
            const int row = lrow + 32 * r;
            CP_ASYNC16(aB + sw128(row * 128 + lc16 * 16),
                       Arow + (long long)row * Kld + k0 + lc16 * 8);
        }
        #pragma unroll
        for (int r = 0; r < BNp / 32; r++) {
            const int row = lrow + 32 * r;
            CP_ASYNC16(bB + sw128(row * 128 + lc16 * 16),
                       Brow + (long long)row * Kld + k0 + lc16 * 8);
        }
    };

    #pragma unroll
    for (int it = 0; it < INFLT; it++) {
        if (it < NC) issue(it, it);
        CP_COMMIT();
    }

    const int aRowL = (lane & 15);
    const int aHiK  = (lane >> 4);
    const int bRowL = ((lane & 16) >> 1) + (lane & 7);
    const int bHiK  = ((lane >> 3) & 1);

    #pragma unroll 1
    for (int it = 0; it < NC; it++) {
        cp_wait<NST - 2>();
        __syncthreads();
        const int nx = it + INFLT;
        if (nx < NC) issue(nx, nx % NST);
        CP_COMMIT();
        const int buf = it % NST;
        const uint32_t aB = sAb + buf * STG_A;
        const uint32_t bB = sBb + buf * STG_B;
        #pragma unroll
        for (int s = 0; s < 4; s++) {
            uint32_t ra[MF][4], rb[NG][4];
            #pragma unroll
            for (int mf = 0; mf < MF; mf++) {
                int row = warpM * WTM + mf * 16 + aRowL;
                int c16 = s * 2 + aHiK;
                LDSM_X4(ra[mf][0], ra[mf][1], ra[mf][2], ra[mf][3],
                        aB + sw128(row * 128 + c16 * 16));
            }
            #pragma unroll
            for (int ng = 0; ng < NG; ng++) {
                int nrow = warpN * WTN + ng * 16 + bRowL;
                int c16 = s * 2 + bHiK;
                LDSM_X4(rb[ng][0], rb[ng][1], rb[ng][2], rb[ng][3],
                        bB + sw128(nrow * 128 + c16 * 16));
            }
            #pragma unroll
            for (int mf = 0; mf < MF; mf++)
                #pragma unroll
                for (int ng = 0; ng < NG; ng++) {
                    MMA16816(acc[mf][ng * 2 + 0], ra[mf], rb[ng][0], rb[ng][1]);
                    MMA16816(acc[mf][ng * 2 + 1], ra[mf], rb[ng][2], rb[ng][3]);
                }
        }
    }

    const float al = g.alpha;

    if (CAUSAL == 0 && g.Vt) {
        __nv_bfloat16 (*st)[136] = (__nv_bfloat16 (*)[136])dsm;
        __syncthreads();
        #pragma unroll
        for (int mf = 0; mf < MF; mf++) {
            const int r_l = warpM * WTM + mf * 16 + (lane >> 2);
            #pragma unroll
            for (int nf = 0; nf < NG * 2; nf++) {
                const int c_l = warpN * WTN + nf * 8 + (lane & 3) * 2;
                st[c_l][r_l]         = __float2bfloat16(acc[mf][nf][0]);
                st[c_l + 1][r_l]     = __float2bfloat16(acc[mf][nf][1]);
                st[c_l][r_l + 8]     = __float2bfloat16(acc[mf][nf][2]);
                st[c_l + 1][r_l + 8] = __float2bfloat16(acc[mf][nf][3]);
            }
        }
        __syncthreads();
        const int rb_ = by >> 3;
        const int s0 = (by & 7) * 128;
        const int d = tid >> 1;
        const int so = (tid & 1) * 64;
        const uint4* src = (const uint4*)&st[d][so];
        uint4* dst = (uint4*)(g.Vt + (long long)rb_ * Dd * Ss
                              + (long long)(bx * BNp + d) * Ss + s0 + so);
        #pragma unroll
        for (int i = 0; i < 8; i++) dst[i] = src[i];
        return;
    }

    __nv_bfloat16* Cb = (CAUSAL == 0) ? (bz == 0 ? g.Cb0 : g.Cb1) : nullptr;
    float* Cf = g.Cf;
    #pragma unroll
    for (int mf = 0; mf < MF; mf++) {
        const long long r0 = (long long)(by * BMp + warpM * WTM + mf * 16 + (lane >> 2));
        const long long r1 = r0 + 8;
        #pragma unroll
        for (int nf = 0; nf < NG * 2; nf++) {
            const int c0 = bx * BNp + warpN * WTN + nf * 8 + (lane & 3) * 2;
            float v00 = acc[mf][nf][0] * al, v01 = acc[mf][nf][1] * al;
            float v10 = acc[mf][nf][2] * al, v11 = acc[mf][nf][3] * al;
            if (CAUSAL == 0) {
                __nv_bfloat162 p0, p1;
                p0.x = __float2bfloat16(v00); p0.y = __float2bfloat16(v01);
                p1.x = __float2bfloat16(v10); p1.y = __float2bfloat16(v11);
                *(__nv_bfloat162*)(Cb + bz * g.sC + r0 * g.N + c0) = p0;
                *(__nv_bfloat162*)(Cb + bz * g.sC + r1 * g.N + c0) = p1;
            } else {
                *(float2*)(Cf + bz * g.sC + r0 * g.N + c0) = make_float2(v00, v01);
                *(float2*)(Cf + bz * g.sC + r1 * g.N + c0) = make_float2(v10, v11);
            }
        }
    }
}

constexpr int SM_QK  = (128 + 128) * 128 * 3;   // 98304, 2 CTA/SM
constexpr int SM_V   = (128 + 128) * 128 * 5;   // 163840, 1 CTA/SM
constexpr int SM_SC  = (128 + 64) * 128 * 5;    // 122880, 1 CTA/SM
constexpr int SM_PV  = (64 + 128) * 128 * 3;    // 73728, 2 CTA/SM

// ---------------- elementwise bf16 cast ----------------
__global__ __launch_bounds__(256)
void splitH_kernel(const float* __restrict__ in, __nv_bfloat16* __restrict__ h, int n)
{
    int i = blockIdx.x * 256 + threadIdx.x;
    if (i < n) h[i] = __float2bfloat16(in[i]);
}

// merged 3-weight transpose
struct TW3 { const float *i0, *i1, *i2; __nv_bfloat16 *h0, *h1, *h2; };
__global__ __launch_bounds__(256)
void transpose_w3(TW3 a)
{
    const int z = blockIdx.z;
    const float* in = (z == 0 ? a.i0 : z == 1 ? a.i1 : a.i2);
    __nv_bfloat16* oh = (z == 0 ? a.h0 : z == 1 ? a.h1 : a.h2);
    __shared__ float t[32][33];
    const int c0 = blockIdx.x * 32, r0 = blockIdx.y * 32;
    const int x = threadIdx.x & 31, y = threadIdx.x >> 5;
    #pragma unroll
    for (int r = y; r < 32; r += 8) t[r][x] = in[(long long)(r0 + r) * Dd + c0 + x];
    __syncthreads();
    #pragma unroll
    for (int r = y; r < 32; r += 8)
        oh[(long long)(c0 + r) * Dd + r0 + x] = __float2bfloat16(t[x][r]);
}

// ---------------- positions + splat influence: 4 tokens / 256 threads ----------------
__global__ __launch_bounds__(256)
void pos_influence_kernel(const float* __restrict__ x, const float* __restrict__ posW,
                          const float* __restrict__ posB, const float* __restrict__ posBias,
                          const float* __restrict__ splatPos, const float* __restrict__ logScales,
                          float* __restrict__ wout)
{
    const int t0 = blockIdx.x * 4;
    const int b = t0 >> 10;
    const int s0 = t0 & 1023;
    __shared__ float xs[4][Dd];
    __shared__ float pos[4][Ee];
    const int tid = threadIdx.x;
    const int e = tid & 63, tg = tid >> 6;
    for (int i = tid; i < 4 * Dd; i += 256)
        xs[i >> 10][i & 1023] = x[(long long)t0 * Dd + i];
    __syncthreads();
    float acc = posB[e];
    const float* xr = xs[tg];
    #pragma unroll 8
    for (int d = 0; d < Dd; d++) acc += xr[d] * __ldg(&posW[d * Ee + e]);
    pos[tg][e] = tanhf(acc) + posBias[(s0 + tg) * Ee + e];
    __syncthreads();
    if (tid < 64) {
        const int n = tid & 15, tk = tid >> 4;
        float sc = expf(logScales[n]);
        sc = fminf(fmaxf(sc, 0.3f), 2.0f);
        float dsq = 0.0f;
        #pragma unroll
        for (int j = 0; j < Ee; j++) {
            float d = pos[tk][j] - splatPos[n * Ee + j];
            dsq += d * d;
        }
        float inf = fmaxf(__expf(-0.5f * dsq / (sc * sc)), 0.01f);
        wout[((long long)b * Nn + n) * Ss + s0 + tk] = inf;
    }
}

// ---------------- aggregated softmax -> P̄ (bf16), block-per-row ----------------
// Pointers pre-offset to one batch; grid = Ss blocks.
__global__ __launch_bounds__(256)
void pbar_kernel(const float* __restrict__ Abuf, const float* __restrict__ wbuf,
                 const float* __restrict__ gates, __nv_bfloat16* __restrict__ Phi)
{
    __shared__ __nv_bfloat16 sE[Nn][Ss];     // 32KB
    __shared__ float red[8][Nn];
    __shared__ float gscS[Nn];
    const int i = blockIdx.x;
    const float* Arow = Abuf + ((long long)i << 10);
    const int tid = threadIdx.x, lane = tid & 31, wd = tid >> 5;
    const int len = i + 1;

    float aL[4];
    #pragma unroll
    for (int k = 0; k < 4; k++) {
        int j = tid + k * 256;
        aL[k] = (j < len) ? Arow[j] : 0.0f;
    }

    float s[Nn];
    #pragma unroll
    for (int n = 0; n < Nn; n++) {
        const float* wrow = wbuf + (n << 10);
        const float wi = wrow[i];
        float sn = 0.0f;
        #pragma unroll
        for (int k = 0; k < 4; k++) {
            int j = tid + k * 256;
            float e = 0.0f;
            if (j < len) e = __expf(wi * wrow[j] * aL[k]);
            sE[n][j] = __float2bfloat16(e);
            sn += e;
        }
        s[n] = sn;
    }
    #pragma unroll
    for (int n = 0; n < Nn; n++) s[n] = warpSum(s[n]);
    if (lane == 0) {
        #pragma unroll
        for (int n = 0; n < Nn; n++) red[wd][n] = s[n];
    }
    __syncthreads();
    if (tid < Nn) {
        float t = 0.0f;
        #pragma unroll
        for (int ww = 0; ww < 8; ww++) t += red[ww][tid];
        gscS[tid] = (1.0f / (1.0f + __expf(-gates[tid]))) / (16.0f * t);
    }
    __syncthreads();

    float accL[4] = {0, 0, 0, 0};
    #pragma unroll
    for (int n = 0; n < Nn; n++) {
        const float gsc = gscS[n];
        #pragma unroll
        for (int k = 0; k < 4; k++) {
            int j = tid + k * 256;
            accL[k] += gsc * __bfloat162float(sE[n][j]);
        }
    }
    __nv_bfloat16* ph = Phi + ((long long)i << 10);
    #pragma unroll
    for (int k = 0; k < 4; k++) {
        int j = tid + k * 256;
        ph[j] = __float2bfloat16(accL[k]);
    }
}

// ---------------- residual + LayerNorm ----------------
__global__ __launch_bounds__(256)
void final_ln_kernel(const float* __restrict__ x, const float* __restrict__ comb,
                     const float* __restrict__ rwp, const float* __restrict__ lnw,
                     const float* __restrict__ lnb, float* __restrict__ out)
{
    const int row = blockIdx.x;
    const int tid = threadIdx.x;
    __shared__ float red[9];
    const float rw = 1.0f / (1.0f + expf(-rwp[0]));
    const float om = 1.0f - rw;
    const float4 xv = ((const float4*)(x + (long long)row * Dd))[tid];
    const float4 cv = ((const float4*)(comb + (long long)row * Dd))[tid];
    float o0 = rw * xv.x + om * cv.x;
    float o1 = rw * xv.y + om * cv.y;
    float o2 = rw * xv.z + om * cv.z;
    float o3 = rw * xv.w + om * cv.w;
    float s = o0 + o1 + o2 + o3;
    float sq = o0 * o0 + o1 * o1 + o2 * o2 + o3 * o3;
    s = blockSum(s, red);
    __syncthreads();
    sq = blockSum(sq, red);
    const float mean = s * (1.0f / Dd);
    const float var = sq * (1.0f / Dd) - mean * mean;
    const float rstd = rsqrtf(var + 1e-5f);
    const float4 wv = ((const float4*)lnw)[tid];
    const float4 bv = ((const float4*)lnb)[tid];
    float4 ov;
    ov.x = (o0 - mean) * rstd * wv.x + bv.x;
    ov.y = (o1 - mean) * rstd * wv.y + bv.y;
    ov.z = (o2 - mean) * rstd * wv.z + bv.z;
    ov.w = (o3 - mean) * rstd * wv.w + bv.w;
    ((float4*)(out + (long long)row * Dd))[tid] = ov;
}

// ---------------- host launcher ----------------
static cudaStream_t g_s1, g_s2;
static cudaEvent_t g_evF1, g_evF2, g_evX, g_evJ1, g_evJ2, g_evV, g_evQK, g_evPV1;

extern "C" void kernel_launch(void* const* d_in, const int* in_sizes, int n_in,
                              void* d_out, int out_size)
{
    const float* x        = (const float*)d_in[0];
    const float* posW     = (const float*)d_in[1];
    const float* posB     = (const float*)d_in[2];
    const float* posBias  = (const float*)d_in[3];
    const float* splatPos = (const float*)d_in[4];
    const float* logSc    = (const float*)d_in[5];
    const float* qW       = (const float*)d_in[6];
    const float* kW       = (const float*)d_in[7];
    const float* vW       = (const float*)d_in[8];
    const float* gates    = (const float*)d_in[9];
    const float* rwp      = (const float*)d_in[10];
    const float* lnw      = (const float*)d_in[11];
    const float* lnb      = (const float*)d_in[12];
    float* out = (float*)d_out;

    static bool inited = []() {
        cudaFuncSetAttribute((const void*)hmma_gemm<0, 128, 128, 4, 2, 3>,
                             cudaFuncAttributeMaxDynamicSharedMemorySize, SM_QK);
        cudaFuncSetAttribute((const void*)hmma_gemm<0, 128, 128, 4, 2, 5>,
                             cudaFuncAttributeMaxDynamicSharedMemorySize, SM_V);
        cudaFuncSetAttribute((const void*)hmma_gemm<1, 128, 64, 4, 2, 5>,
                             cudaFuncAttributeMaxDynamicSharedMemorySize, SM_SC);
        cudaFuncSetAttribute((const void*)hmma_gemm<2, 64, 128, 2, 4, 3>,
                             cudaFuncAttributeMaxDynamicSharedMemorySize, SM_PV);
        cudaStreamCreateWithFlags(&g_s1, cudaStreamNonBlocking);
        cudaStreamCreateWithFlags(&g_s2, cudaStreamNonBlocking);
        cudaEventCreateWithFlags(&g_evF1, cudaEventDisableTiming);
        cudaEventCreateWithFlags(&g_evF2, cudaEventDisableTiming);
        cudaEventCreateWithFlags(&g_evX, cudaEventDisableTiming);
        cudaEventCreateWithFlags(&g_evJ1, cudaEventDisableTiming);
        cudaEventCreateWithFlags(&g_evJ2, cudaEventDisableTiming);
        cudaEventCreateWithFlags(&g_evV, cudaEventDisableTiming);
        cudaEventCreateWithFlags(&g_evQK, cudaEventDisableTiming);
        cudaEventCreateWithFlags(&g_evPV1, cudaEventDisableTiming);
        return true;
    }();
    (void)inited;

    float *A, *comb, *w;
    __nv_bfloat16 *xh, *wqh, *wkh, *wvh, *Qh, *Kh, *Vth, *Ph;
    cudaGetSymbolAddress((void**)&A, g_A);
    cudaGetSymbolAddress((void**)&comb, g_comb);
    cudaGetSymbolAddress((void**)&w, g_w);
    cudaGetSymbolAddress((void**)&xh, g_xh);
    cudaGetSymbolAddress((void**)&wqh, g_wqh);
    cudaGetSymbolAddress((void**)&wkh, g_wkh);
    cudaGetSymbolAddress((void**)&wvh, g_wvh);
    cudaGetSymbolAddress((void**)&Qh, g_Qh);
    cudaGetSymbolAddress((void**)&Kh, g_Kh);
    cudaGetSymbolAddress((void**)&Vth, g_Vth);
    cudaGetSymbolAddress((void**)&Ph, g_Ph);

    const float inv_sqrt_d = 1.0f / 32.0f;
    const long long SD = (long long)Ss * Dd;
    const long long SSq = (long long)Ss * Ss;

    // fork: pos_influence on s1 (b1 tail chain follows on s1)
    cudaEventRecord(g_evF1, 0);
    cudaStreamWaitEvent(g_s1, g_evF1, 0);
    pos_influence_kernel<<<Mtot / 4, 256, 0, g_s1>>>(x, posW, posB, posBias, splatPos, logSc, w);
    cudaEventRecord(g_evJ1, g_s1);

    // fork: weight transpose on s2
    cudaEventRecord(g_evF2, 0);
    cudaStreamWaitEvent(g_s2, g_evF2, 0);
    {
        TW3 tw = { qW, kW, vW, wqh, wkh, wvh };
        transpose_w3<<<dim3(32, 32, 3), 256, 0, g_s2>>>(tw);
    }
    cudaEventRecord(g_evJ2, g_s2);

    // main: x -> bf16
    splitH_kernel<<<(Mtot * Dd) / 256, 256>>>(x, xh, Mtot * Dd);
    cudaEventRecord(g_evX, 0);

    // V projection on s2 (needs xh + wvh); deep pipeline, off critical path
    cudaStreamWaitEvent(g_s2, g_evX, 0);
    {
        GemmArgs a = {};
        a.A = xh; a.sA = 0;
        a.B0 = wvh; a.B1 = wvh; a.B2 = wvh; a.sB = 0;
        a.Vt = Vth; a.sC = 0;
        a.M = Mtot; a.N = Dd; a.K = Dd; a.alpha = 1.0f;
        hmma_gemm<0, 128, 128, 4, 2, 5><<<dim3(Dd / 128, Mtot / 128, 1), 256, SM_V, g_s2>>>(a);
    }
    cudaEventRecord(g_evV, g_s2);

    // main: Q,K projections
    cudaStreamWaitEvent(0, g_evJ2, 0);
    {
        GemmArgs a = {};
        a.A = xh; a.sA = 0;
        a.B0 = wqh; a.B1 = wkh; a.B2 = wkh; a.sB = 0;
        a.Cb0 = Qh; a.Cb1 = Kh; a.sC = 0;
        a.M = Mtot; a.N = Dd; a.K = Dd; a.alpha = 1.0f;
        hmma_gemm<0, 128, 128, 4, 2, 3><<<dim3(Dd / 128, Mtot / 128, 2), 256, SM_QK>>>(a);
    }
    cudaEventRecord(g_evQK, 0);

    // ---- batch-pipelined tail: b0 on main, b1 on s1 ----
    // score b0 (main)
    {
        GemmArgs a = {};
        a.A = Qh; a.sA = 0;
        a.B0 = Kh; a.B1 = Kh; a.B2 = Kh; a.sB = 0;
        a.Cf = A; a.sC = 0;
        a.M = Ss; a.N = Ss; a.K = Dd; a.alpha = inv_sqrt_d;
        hmma_gemm<1, 128, 64, 4, 2, 5><<<dim3(Ss / 64, Ss / 128, 1), 256, SM_SC>>>(a);
    }
    // score b1 (s1; after QK — s1 already ordered after pos_influence)
    cudaStreamWaitEvent(g_s1, g_evQK, 0);
    {
        GemmArgs a = {};
        a.A = Qh + SD; a.sA = 0;
        a.B0 = Kh + SD; a.B1 = a.B0; a.B2 = a.B0; a.sB = 0;
        a.Cf = A + SSq; a.sC = 0;
        a.M = Ss; a.N = Ss; a.K = Dd; a.alpha = inv_sqrt_d;
        hmma_gemm<1, 128, 64, 4, 2, 5><<<dim3(Ss / 64, Ss / 128, 1), 256, SM_SC, g_s1>>>(a);
    }
    // pbar b0 (main; needs w from s1's pos_influence)
    cudaStreamWaitEvent(0, g_evJ1, 0);
    pbar_kernel<<<Ss, 256>>>(A, w, gates, Ph);
    // pbar b1 (s1; in-order after score b1; w written on s1)
    pbar_kernel<<<Ss, 256, 0, g_s1>>>(A + SSq, w + Nn * Ss, gates, Ph + SSq);
    // PV b0 (main; needs V)
    cudaStreamWaitEvent(0, g_evV, 0);
    {
        GemmArgs a = {};
        a.A = Ph; a.sA = 0;
        a.B0 = Vth; a.B1 = Vth; a.B2 = Vth; a.sB = 0;
        a.Cf = comb; a.sC = 0;
        a.M = Ss; a.N = Dd; a.K = Ss; a.alpha = 1.0f;
        hmma_gemm<2, 64, 128, 2, 4, 3><<<dim3(Dd / 128, Ss / 64, 1), 256, SM_PV>>>(a);
    }
    // PV b1 (s1; needs V)
    cudaStreamWaitEvent(g_s1, g_evV, 0);
    {
        GemmArgs a = {};
        a.A = Ph + SSq; a.sA = 0;
        a.B0 = Vth + (long long)Dd * Ss; a.B1 = a.B0; a.B2 = a.B0; a.sB = 0;
        a.Cf = comb + SD; a.sC = 0;
        a.M = Ss; a.N = Dd; a.K = Ss; a.alpha = 1.0f;
        hmma_gemm<2, 64, 128, 2, 4, 3><<<dim3(Dd / 128, Ss / 64, 1), 256, SM_PV, g_s1>>>(a);
    }
    cudaEventRecord(g_evPV1, g_s1);

    // residual + LayerNorm (join both batches)
    cudaStreamWaitEvent(0, g_evPV1, 0);
    final_ln_kernel<<<Mtot, 256>>>(x, comb, rwp, lnw, lnb, out);
}